// round 15
// baseline (speedup 1.0000x reference)
#include <cuda_runtime.h>
#include <cuda_fp16.h>
#include <math.h>

#define NN    50000      // nodes
#define NNP   50048      // padded to 16*8*391
#define NE    800000     // edges
#define NG    512        // graphs
#define HID   128
#define RBF   32
#define NL    6
#define TBL   1280       // LUT grid points per layer (fits 12 bits)
#define DMAX  5.0f       // beyond this, rbf == 0 to fp32 precision
#define SBLK  196        // scan blocks (196*256 >= NN)
#define SCAP  128        // per-warp smem sort capacity

typedef unsigned long long u64;
typedef unsigned int u32;

// ---------------- device scratch (static allocations only) ----------------
__device__ float  g_h    [NNP * HID];      // node features fp32 (mlp input)
__device__ __half g_hh   [NNP * HID];      // node features fp16 (edge gather)
__device__ float  g_aggr [NNP * HID];      // aggregated messages
__device__ float  g_table[NL * TBL * HID]; // W_l(d) lookup table
__device__ int    g_deg  [NN];
__device__ float  g_invd [NN];
__device__ int    g_off  [NN + 1];
__device__ int    g_cur  [NN];
__device__ int    g_bsum [SBLK];           // scan partials
__device__ int    g_tick;                  // scan grid-barrier ticket
__device__ int    g_pk   [NE];             // packed edge: [far(1)|idx(12)|j(16)]
// mma-fragment-layout fp16 weight images (hi only):
// [m:14][s:8][t:16][lane:32][2 x u32: bh0,bh1]
__device__ u32    g_wfrag[14 * 8 * 16 * 32 * 2];

__device__ __forceinline__ float sspf(float x) {
    return fmaxf(x, 0.0f) + log1pf(expf(-fabsf(x))) - 0.5f;
}

// pack two floats as f16x2
__device__ __forceinline__ u32 packh2(float x, float y) {
    __half2 h = __floats2half2_rn(x, y);
    return *reinterpret_cast<u32*>(&h);
}
// fp16 hi/lo split of a float2 into packed f16x2 pair
__device__ __forceinline__ void splith2(float x, float y, u32& hi, u32& lo) {
    __half hx = __float2half_rn(x);
    __half hy = __float2half_rn(y);
    float rx = x - __half2float(hx);
    float ry = y - __half2float(hy);
    __half2 hh = __halves2half2(hx, hy);
    hi = *reinterpret_cast<u32*>(&hh);
    lo = packh2(rx, ry);
}

__device__ __forceinline__ void mma_h(float c[4], const u32 a[4], u32 b0, u32 b1) {
    asm volatile(
        "mma.sync.aligned.m16n8k16.row.col.f32.f16.f16.f32 "
        "{%0,%1,%2,%3}, {%4,%5,%6,%7}, {%8,%9}, {%0,%1,%2,%3};"
        : "+f"(c[0]), "+f"(c[1]), "+f"(c[2]), "+f"(c[3])
        : "r"(a[0]), "r"(a[1]), "r"(a[2]), "r"(a[3]), "r"(b0), "r"(b1));
}

// --- init: h = embed[z] (fp32+fp16), zero deg/tick/tails, zero energy out --
__global__ void k_init(const int* __restrict__ z, const float* __restrict__ embed,
                       float* __restrict__ out) {
    int tid  = blockIdx.x * blockDim.x + threadIdx.x;   // NNP*32 threads exactly
    if (tid < NG) out[tid] = 0.0f;                      // energy accumulator
    if (tid == 0) g_tick = 0;                           // scan barrier reset
    int n    = tid >> 5;
    int lane = tid & 31;
    if (n >= NN) {                                      // padded tail: keep zero
        float4 zf = make_float4(0.f, 0.f, 0.f, 0.f);
        *(float4*)(g_h    + (size_t)n * HID + lane * 4) = zf;
        *(float4*)(g_aggr + (size_t)n * HID + lane * 4) = zf;
        *(uint2*) (g_hh   + (size_t)n * HID + lane * 4) = make_uint2(0u, 0u);
        return;
    }
    if (lane == 0) g_deg[n] = 0;
    int zz = z[n];
    float4 v = *(const float4*)(embed + (size_t)zz * HID + lane * 4);
    *(float4*)(g_h + (size_t)n * HID + lane * 4) = v;
    uint2 up;
    up.x = packh2(v.x, v.y);
    up.y = packh2(v.z, v.w);
    *(uint2*)(g_hh + (size_t)n * HID + lane * 4) = up;
}

// ---------------- degree count ----------------
__global__ void k_deg(const int* __restrict__ ei) {
    int e = blockIdx.x * blockDim.x + threadIdx.x;      // NE threads exactly
    atomicAdd(&g_deg[ei[e]], 1);
}

// ------ single-kernel scan: 196 co-resident blocks + ticket grid barrier ---
__global__ void k_scanf() {
    __shared__ int sm[256];
    int t = threadIdx.x;
    int n = blockIdx.x * 256 + t;
    int d = (n < NN) ? g_deg[n] : 0;
    sm[t] = d;
    __syncthreads();
    for (int o = 1; o < 256; o <<= 1) {
        int v = (t >= o) ? sm[t - o] : 0;
        __syncthreads();
        sm[t] += v;
        __syncthreads();
    }
    int local = sm[t] - d;                  // block-local exclusive prefix
    if (t == 255) {
        g_bsum[blockIdx.x] = sm[255];
        __threadfence();
        atomicAdd(&g_tick, 1);
    }
    if (t == 0) {
        while (*(volatile int*)&g_tick < SBLK) { }
        __threadfence();
    }
    __syncthreads();
    // base = sum of bsum[0..blockIdx)
    int v2 = (t < blockIdx.x) ? g_bsum[t] : 0;   // blockIdx < SBLK <= 256
    sm[t] = v2;
    __syncthreads();
    for (int o = 128; o > 0; o >>= 1) {
        if (t < o) sm[t] += sm[t + o];
        __syncthreads();
    }
    int base = sm[0];
    if (n < NN) {
        int off = local + base;
        g_off[n]  = off;
        g_cur[n]  = off;
        g_invd[n] = 1.0f / (float)max(d, 1);
        if (n == NN - 1) g_off[NN] = off + d;
    }
}

// -------- compute d, pack [far|idx|j], scatter into CSR buckets ------------
__global__ void k_scatter(const int* __restrict__ ei, const float* __restrict__ pos) {
    int e = blockIdx.x * blockDim.x + threadIdx.x;      // NE threads exactly
    int i = ei[e];
    int j = ei[NE + e];
    float dx = pos[3 * i + 0] - pos[3 * j + 0];
    float dy = pos[3 * i + 1] - pos[3 * j + 1];
    float dz = pos[3 * i + 2] - pos[3 * j + 2];
    float d  = sqrtf(dx * dx + dy * dy + dz * dz);
    const float inv_step = (float)(TBL - 1) / DMAX;
    float tt = fminf(d * inv_step, (float)(TBL - 1));
    int pk;
    if (tt >= (float)(TBL - 1)) {
        pk = (int)(0x80000000u) | j;                    // far: bit31 set, idx=0
    } else {
        int idx = min((int)(tt + 0.5f), TBL - 1);       // nearest table row
        pk = (idx << 16) | j;
    }
    int p = atomicAdd(&g_cur[i], 1);
    g_pk[p] = pk;
}

// --- deterministic order: warp-per-node odd-even sort by packed word -------
// equal keys => identical payloads (same far/idx/j) => order irrelevant
__global__ void k_sort() {
    __shared__ int pk[8][SCAP];
    int tid  = threadIdx.x;
    int wid  = tid >> 5;
    int lane = tid & 31;
    int n    = (blockIdx.x * blockDim.x + tid) >> 5;    // 6250*8 = 50000 exact
    int lo = g_off[n], hi = g_off[n + 1];
    int d  = hi - lo;
    if (d <= 1) return;
    if (d > SCAP) {                                     // fallback (never hit @Poisson16)
        if (lane == 0) {
            for (int a = lo + 1; a < hi; a++) {
                int k = g_pk[a];
                int b = a - 1;
                while (b >= lo && g_pk[b] > k) {
                    g_pk[b + 1] = g_pk[b];
                    b--;
                }
                g_pk[b + 1] = k;
            }
        }
        return;
    }
    for (int u = lane; u < d; u += 32)
        pk[wid][u] = g_pk[lo + u];
    __syncwarp();
    for (int p = 0; p < d; p++) {
        int st = p & 1;
        for (int k2 = lane; 2 * k2 + 1 + st < d; k2 += 32) {
            int a = st + 2 * k2;
            int ka = pk[wid][a], kb = pk[wid][a + 1];
            if (ka > kb) {
                pk[wid][a] = kb;
                pk[wid][a + 1] = ka;
            }
        }
        __syncwarp();
    }
    for (int u = lane; u < d; u += 32)
        g_pk[lo + u] = pk[wid][u];
}

// ---------------- build W_l(d) table: 8 grid points per block --------------
__global__ void k_table(const float* __restrict__ fw1, const float* __restrict__ fb1,
                        const float* __restrict__ fw2, const float* __restrict__ fb2) {
    const int PG = 8;
    int gid = blockIdx.x * PG;          // over NL*TBL
    int l   = gid / TBL;
    int g0  = gid - l * TBL;
    int c   = threadIdx.x;              // 128 threads
    __shared__ float rbf [PG][RBF];
    __shared__ float sspt[PG][HID];
    const float step   = DMAX / (float)(TBL - 1);
    const float cspace = 4.0f / 31.0f;

    for (int u = c; u < PG * RBF; u += HID) {
        int p = u >> 5, k = u & 31;
        float d = (float)(g0 + p) * step;
        float x = d - (float)k * cspace;
        rbf[p][k] = expf(-32.0f * x * x);
    }
    __syncthreads();

    float acc[PG];
    float b1 = fb1[l * HID + c];
    #pragma unroll
    for (int p = 0; p < PG; p++) acc[p] = b1;
    for (int k = 0; k < RBF; k++) {
        float f = fw1[(size_t)(l * RBF + k) * HID + c];
        #pragma unroll
        for (int p = 0; p < PG; p++) acc[p] = fmaf(rbf[p][k], f, acc[p]);
    }
    #pragma unroll
    for (int p = 0; p < PG; p++) sspt[p][c] = sspf(acc[p]);
    __syncthreads();

    float b2 = fb2[l * HID + c];
    #pragma unroll
    for (int p = 0; p < PG; p++) acc[p] = b2;
    for (int m = 0; m < HID; m++) {
        float f = fw2[(size_t)(l * HID + m) * HID + c];
        #pragma unroll
        for (int p = 0; p < PG; p++) acc[p] = fmaf(sspt[p][m], f, acc[p]);
    }
    #pragma unroll
    for (int p = 0; p < PG; p++)
        g_table[((size_t)l * TBL + g0 + p) * HID + c] = acc[p];
}

// -------- weight images in mma B-fragment layout (fp16 hi only) ------------
__global__ void k_prepw(const float* __restrict__ uw1, const float* __restrict__ uw2,
                        const float* __restrict__ ow1, const float* __restrict__ ow2) {
    int idx  = blockIdx.x * blockDim.x + threadIdx.x;   // 14*8*16*32 threads exactly
    int lane = idx & 31;
    int t    = (idx >> 5) & 15;
    int s    = (idx >> 9) & 7;
    int m    = idx >> 12;
    const float* W;
    if (m < 12)       W = (m & 1) ? (uw2 + (size_t)(m >> 1) * 16384)
                                  : (uw1 + (size_t)(m >> 1) * 16384);
    else if (m == 12) W = ow1;
    else              W = ow2;
    int g    = lane >> 2;
    int tid2 = (lane & 3) * 2;
    int n    = t * 8 + g;
    int k0   = s * 16 + tid2;
    float v00 = W[(size_t)k0 * HID + n];
    float v01 = W[(size_t)(k0 + 1) * HID + n];
    float v10 = W[(size_t)(k0 + 8) * HID + n];
    float v11 = W[(size_t)(k0 + 9) * HID + n];
    uint2 o;
    o.x = packh2(v00, v01);
    o.y = packh2(v10, v11);
    *(uint2*)(g_wfrag + (size_t)idx * 2) = o;
}

// --------- per-layer edge aggregation: one warp per node --------------------
// packed edge word: bit31=far, bits[16:28)=nearest table row, bits[0:16)=j.
// h gathered in fp16 (256B/row, half the LTS bytes), fp32 accumulation.
__global__ void k_edge(int l) {
    int w    = (blockIdx.x * blockDim.x + threadIdx.x) >> 5;  // == node, exact
    int lane = threadIdx.x & 31;
    int lo = g_off[w], hi = g_off[w + 1];
    const float* tab = g_table + (size_t)l * TBL * HID;
    const float4 wlast = *(const float4*)(tab + (size_t)(TBL - 1) * HID + lane * 4);
    float nx = 0.f, ny = 0.f, nz = 0.f, nw = 0.f;   // near accum
    float fx = 0.f, fy = 0.f, fz = 0.f, fw = 0.f;   // far accum (h sum)
    for (int e = lo; e < hi; e++) {
        int p = __ldg(&g_pk[e]);
        int j = p & 0xFFFF;
        uint2 u = __ldg((const uint2*)(g_hh + (size_t)j * HID + lane * 4));
        float2 h01 = __half22float2(*reinterpret_cast<__half2*>(&u.x));
        float2 h23 = __half22float2(*reinterpret_cast<__half2*>(&u.y));
        if (p < 0) {                                 // far (lane-uniform)
            fx += h01.x; fy += h01.y; fz += h23.x; fw += h23.y;
        } else {
            int idx = (p >> 16) & 0xFFF;
            float4 wl = *(const float4*)(tab + (size_t)idx * HID + lane * 4);
            nx = fmaf(h01.x, wl.x, nx);
            ny = fmaf(h01.y, wl.y, ny);
            nz = fmaf(h23.x, wl.z, nz);
            nw = fmaf(h23.y, wl.w, nw);
        }
    }
    float s = g_invd[w];
    float4 o;
    o.x = fmaf(fx, wlast.x, nx) * s;
    o.y = fmaf(fy, wlast.y, ny) * s;
    o.z = fmaf(fz, wlast.z, nz) * s;
    o.w = fmaf(fw, wlast.w, nw) * s;
    *(float4*)(g_aggr + (size_t)w * HID + lane * 4) = o;
}

// ---------- tensor-core fused 2-layer MLP (mma.sync fp16, 2-term split) ----
// Y = act2( ssp(X@W1+b1) @ W2 + b2 ). Each warp: 16 rows x 128 cols, K=128.
// ACT2=0: linear out (+ fp16 shadow if HOUT); ACT2=2: output block — ssp then
// e_atom = Y·ow3 + ob3 reduced per row and atomically added into out[batch].
template <int ACT2, int HOUT>
__global__ void __launch_bounds__(256, 1)
k_mlp_mma(const float* __restrict__ X,
          const u32* __restrict__ WF1, const float* __restrict__ B1,
          const u32* __restrict__ WF2, const float* __restrict__ B2,
          float* __restrict__ Y, __half* __restrict__ YH,
          const int* __restrict__ batch, const float* __restrict__ ow3,
          const float* __restrict__ ob3, float* __restrict__ out) {
    const int lane  = threadIdx.x & 31;
    const int warp  = (blockIdx.x * blockDim.x + threadIdx.x) >> 5;  // 0..3127
    const int rbase = warp * 16;                                     // < NNP
    const int g     = lane >> 2;
    const int tid2  = (lane & 3) * 2;
    const float* xr0 = X + (size_t)(rbase + g) * HID;
    const float* xr1 = X + (size_t)(rbase + g + 8) * HID;

    float acc[16][4];
    #pragma unroll
    for (int t = 0; t < 16; t++)
        #pragma unroll
        for (int q = 0; q < 4; q++) acc[t][q] = 0.f;

    // ---------------- stage 1 ----------------
    const uint2* wf1 = (const uint2*)WF1;
    #pragma unroll
    for (int s = 0; s < 8; s++) {
        int k0 = s * 16 + tid2;
        float2 x00 = *(const float2*)(xr0 + k0);
        float2 x10 = *(const float2*)(xr1 + k0);
        float2 x01 = *(const float2*)(xr0 + k0 + 8);
        float2 x11 = *(const float2*)(xr1 + k0 + 8);
        u32 ah[4], al[4];
        splith2(x00.x, x00.y, ah[0], al[0]);
        splith2(x10.x, x10.y, ah[1], al[1]);
        splith2(x01.x, x01.y, ah[2], al[2]);
        splith2(x11.x, x11.y, ah[3], al[3]);
        const uint2* bp = wf1 + (size_t)s * 512 + lane;
        #pragma unroll
        for (int t = 0; t < 16; t++) {
            uint2 b = __ldg(bp + t * 32);           // bh0,bh1
            mma_h(acc[t], ah, b.x, b.y);
            mma_h(acc[t], al, b.x, b.y);
        }
    }

    // ---- epilogue 1: bias + ssp, D frags -> stage-2 A frags (in register) --
    u32 a2h[8][4], a2l[8][4];
    #pragma unroll
    for (int s = 0; s < 8; s++) {
        #pragma unroll
        for (int hf = 0; hf < 2; hf++) {
            int t = 2 * s + hf;
            float2 bias = *(const float2*)(B1 + t * 8 + tid2);
            float d0 = sspf(acc[t][0] + bias.x);
            float d1 = sspf(acc[t][1] + bias.y);
            float d2 = sspf(acc[t][2] + bias.x);
            float d3 = sspf(acc[t][3] + bias.y);
            splith2(d0, d1, a2h[s][2 * hf + 0], a2l[s][2 * hf + 0]);
            splith2(d2, d3, a2h[s][2 * hf + 1], a2l[s][2 * hf + 1]);
        }
    }

    #pragma unroll
    for (int t = 0; t < 16; t++)
        #pragma unroll
        for (int q = 0; q < 4; q++) acc[t][q] = 0.f;

    // ---------------- stage 2 ----------------
    const uint2* wf2 = (const uint2*)WF2;
    #pragma unroll
    for (int s = 0; s < 8; s++) {
        const uint2* bp = wf2 + (size_t)s * 512 + lane;
        #pragma unroll
        for (int t = 0; t < 16; t++) {
            uint2 b = __ldg(bp + t * 32);
            mma_h(acc[t], a2h[s], b.x, b.y);
            mma_h(acc[t], a2l[s], b.x, b.y);
        }
    }

    // ---- epilogue 2 ----
    if (ACT2 == 2) {
        // output block: ssp, dot with ow3, reduce 4 lanes per row, atomic add
        float p0 = 0.f, p1 = 0.f;
        #pragma unroll
        for (int t = 0; t < 16; t++) {
            int c0 = t * 8 + tid2;
            float2 bias = *(const float2*)(B2 + c0);
            float2 w3   = make_float2(__ldg(&ow3[c0]), __ldg(&ow3[c0 + 1]));
            float o0 = sspf(acc[t][0] + bias.x);
            float o1 = sspf(acc[t][1] + bias.y);
            float o2 = sspf(acc[t][2] + bias.x);
            float o3 = sspf(acc[t][3] + bias.y);
            p0 = fmaf(o0, w3.x, fmaf(o1, w3.y, p0));
            p1 = fmaf(o2, w3.x, fmaf(o3, w3.y, p1));
        }
        p0 += __shfl_xor_sync(0xffffffffu, p0, 1);
        p0 += __shfl_xor_sync(0xffffffffu, p0, 2);
        p1 += __shfl_xor_sync(0xffffffffu, p1, 1);
        p1 += __shfl_xor_sync(0xffffffffu, p1, 2);
        if ((lane & 3) == 0) {
            float b3 = __ldg(&ob3[0]);
            int r0 = rbase + g;
            int r1 = rbase + g + 8;
            if (r0 < NN) atomicAdd(&out[__ldg(&batch[r0])], p0 + b3);
            if (r1 < NN) atomicAdd(&out[__ldg(&batch[r1])], p1 + b3);
        }
    } else {
        float*  yr0 = Y + (size_t)(rbase + g) * HID;
        float*  yr1 = Y + (size_t)(rbase + g + 8) * HID;
        __half* hr0 = HOUT ? (YH + (size_t)(rbase + g) * HID) : (__half*)0;
        __half* hr1 = HOUT ? (YH + (size_t)(rbase + g + 8) * HID) : (__half*)0;
        #pragma unroll
        for (int t = 0; t < 16; t++) {
            float2 bias = *(const float2*)(B2 + t * 8 + tid2);
            float o0 = acc[t][0] + bias.x;
            float o1 = acc[t][1] + bias.y;
            float o2 = acc[t][2] + bias.x;
            float o3 = acc[t][3] + bias.y;
            *(float2*)(yr0 + t * 8 + tid2) = make_float2(o0, o1);
            *(float2*)(yr1 + t * 8 + tid2) = make_float2(o2, o3);
            if (HOUT) {
                *(u32*)(hr0 + t * 8 + tid2) = packh2(o0, o1);
                *(u32*)(hr1 + t * 8 + tid2) = packh2(o2, o3);
            }
        }
    }
}

// ---------------- launch ----------------
extern "C" void kernel_launch(void* const* d_in, const int* in_sizes, int n_in,
                              void* d_out, int out_size) {
    const int*   z     = (const int*)  d_in[0];
    const float* pos   = (const float*)d_in[1];
    const int*   ei    = (const int*)  d_in[2];
    const int*   batch = (const int*)  d_in[3];
    const float* embed = (const float*)d_in[4];
    const float* fw1   = (const float*)d_in[5];
    const float* fb1   = (const float*)d_in[6];
    const float* fw2   = (const float*)d_in[7];
    const float* fb2   = (const float*)d_in[8];
    const float* uw1   = (const float*)d_in[9];
    const float* ub1   = (const float*)d_in[10];
    const float* uw2   = (const float*)d_in[11];
    const float* ub2   = (const float*)d_in[12];
    const float* ow1   = (const float*)d_in[13];
    const float* ob1   = (const float*)d_in[14];
    const float* ow2   = (const float*)d_in[15];
    const float* ob2   = (const float*)d_in[16];
    const float* ow3   = (const float*)d_in[17];
    const float* ob3   = (const float*)d_in[18];
    float* out = (float*)d_out;

    float  *p_h = nullptr, *p_aggr = nullptr;
    __half *p_hh = nullptr;
    u32    *p_wf = nullptr;
    cudaGetSymbolAddress((void**)&p_h,    g_h);
    cudaGetSymbolAddress((void**)&p_hh,   g_hh);
    cudaGetSymbolAddress((void**)&p_aggr, g_aggr);
    cudaGetSymbolAddress((void**)&p_wf,   g_wfrag);

    // preprocessing (once per launch, amortized over 6 layers)
    k_init   <<<(NNP * 32) / 256, 256>>>(z, embed, out);
    k_deg    <<<NE / 256, 256>>>(ei);
    k_scanf  <<<SBLK, 256>>>();
    k_scatter<<<NE / 256, 256>>>(ei, pos);
    k_sort   <<<(NN * 32) / 256, 256>>>();
    k_table  <<<(NL * TBL) / 8, 128>>>(fw1, fb1, fw2, fb2);
    k_prepw  <<<(14 * 8 * 16 * 32) / 256, 256>>>(uw1, uw2, ow1, ow2);

    const int mma_blocks  = NNP / 128;            // 391 blocks x 8 warps x 16 rows
    const int warp_blocks = (NN * 32) / 256;

    for (int l = 0; l < NL; l++) {
        k_edge<<<warp_blocks, 256>>>(l);
        if (l < NL - 1)
            k_mlp_mma<0, 1><<<mma_blocks, 256>>>(
                p_aggr,
                p_wf + (size_t)(2 * l)     * 8192, ub1 + (size_t)l * HID,
                p_wf + (size_t)(2 * l + 1) * 8192, ub2 + (size_t)l * HID,
                p_h, p_hh, nullptr, nullptr, nullptr, nullptr);
        else
            k_mlp_mma<0, 0><<<mma_blocks, 256>>>(   // last layer: no fp16 shadow
                p_aggr,
                p_wf + (size_t)(2 * l)     * 8192, ub1 + (size_t)l * HID,
                p_wf + (size_t)(2 * l + 1) * 8192, ub2 + (size_t)l * HID,
                p_h, nullptr, nullptr, nullptr, nullptr, nullptr);
    }
    // output block fused with energy reduction
    k_mlp_mma<2, 0><<<mma_blocks, 256>>>(
        p_h,
        p_wf + (size_t)12 * 8192, ob1,
        p_wf + (size_t)13 * 8192, ob2,
        nullptr, nullptr, batch, ow3, ob3, out);
}

// round 16
// speedup vs baseline: 1.0552x; 1.0552x over previous
#include <cuda_runtime.h>
#include <cuda_fp16.h>
#include <math.h>

#define NN    50000      // nodes
#define NNP   50048      // padded to 16*8*391
#define NE    800000     // edges
#define NG    512        // graphs
#define HID   128
#define RBF   32
#define NL    6
#define TBL   1280       // LUT grid points per layer (fits 12 bits)
#define DMAX  5.0f       // beyond this, rbf == 0 to fp32 precision
#define SBLK  196        // scan blocks (196*256 >= NN)
#define SCAP  128        // per-warp smem sort capacity
#define TABBLKS ((NL * TBL) / 8)            // 960 table blocks
#define PWBLKS  ((14 * 8 * 16 * 32) / 128)  // 448 prepw blocks (128 thr)

typedef unsigned long long u64;
typedef unsigned int u32;

// ---------------- device scratch (static allocations only) ----------------
__device__ float g_h    [NNP * HID];       // node features (padded, tail zero)
__device__ float g_aggr [NNP * HID];       // aggregated messages
__device__ float g_table[NL * TBL * HID];  // W_l(d) lookup table
__device__ int   g_deg  [NN];
__device__ float g_invd [NN];
__device__ int   g_off  [NN + 1];
__device__ int   g_cur  [NN];
__device__ int   g_bsum [SBLK];            // scan partials
__device__ int   g_tick;                   // scan grid-barrier ticket
__device__ int   g_pk   [NE];              // packed edge: [far(1)|idx(12)|j(16)]
// mma-fragment-layout fp16 weight images (hi only):
// [m:14][s:8][t:16][lane:32][2 x u32: bh0,bh1]
__device__ u32   g_wfrag[14 * 8 * 16 * 32 * 2];

__device__ __forceinline__ float sspf(float x) {
    return fmaxf(x, 0.0f) + log1pf(expf(-fabsf(x))) - 0.5f;
}

// pack two floats as f16x2
__device__ __forceinline__ u32 packh2(float x, float y) {
    __half2 h = __floats2half2_rn(x, y);
    return *reinterpret_cast<u32*>(&h);
}
// fp16 hi/lo split of a float2 into packed f16x2 pair
__device__ __forceinline__ void splith2(float x, float y, u32& hi, u32& lo) {
    __half hx = __float2half_rn(x);
    __half hy = __float2half_rn(y);
    float rx = x - __half2float(hx);
    float ry = y - __half2float(hy);
    __half2 hh = __halves2half2(hx, hy);
    hi = *reinterpret_cast<u32*>(&hh);
    lo = packh2(rx, ry);
}

__device__ __forceinline__ void mma_h(float c[4], const u32 a[4], u32 b0, u32 b1) {
    asm volatile(
        "mma.sync.aligned.m16n8k16.row.col.f32.f16.f16.f32 "
        "{%0,%1,%2,%3}, {%4,%5,%6,%7}, {%8,%9}, {%0,%1,%2,%3};"
        : "+f"(c[0]), "+f"(c[1]), "+f"(c[2]), "+f"(c[3])
        : "r"(a[0]), "r"(a[1]), "r"(a[2]), "r"(a[3]), "r"(b0), "r"(b1));
}

// --- init: h = embed[z], zero deg/tick, zero padded tail, zero energy out --
__global__ void k_init(const int* __restrict__ z, const float* __restrict__ embed,
                       float* __restrict__ out) {
    int tid  = blockIdx.x * blockDim.x + threadIdx.x;   // NNP*32 threads exactly
    if (tid < NG) out[tid] = 0.0f;                      // energy accumulator
    if (tid == 0) g_tick = 0;                           // scan barrier reset
    int n    = tid >> 5;
    int lane = tid & 31;
    if (n >= NN) {                                      // padded tail: keep zero
        float4 zf = make_float4(0.f, 0.f, 0.f, 0.f);
        *(float4*)(g_h    + (size_t)n * HID + lane * 4) = zf;
        *(float4*)(g_aggr + (size_t)n * HID + lane * 4) = zf;
        return;
    }
    if (lane == 0) g_deg[n] = 0;
    int zz = z[n];
    float4 v = *(const float4*)(embed + (size_t)zz * HID + lane * 4);
    *(float4*)(g_h + (size_t)n * HID + lane * 4) = v;
}

// ---------------- degree count ----------------
__global__ void k_deg(const int* __restrict__ ei) {
    int e = blockIdx.x * blockDim.x + threadIdx.x;      // NE threads exactly
    atomicAdd(&g_deg[ei[e]], 1);
}

// ------ single-kernel scan: 196 co-resident blocks + ticket grid barrier ---
__global__ void k_scanf() {
    __shared__ int sm[256];
    int t = threadIdx.x;
    int n = blockIdx.x * 256 + t;
    int d = (n < NN) ? g_deg[n] : 0;
    sm[t] = d;
    __syncthreads();
    for (int o = 1; o < 256; o <<= 1) {
        int v = (t >= o) ? sm[t - o] : 0;
        __syncthreads();
        sm[t] += v;
        __syncthreads();
    }
    int local = sm[t] - d;                  // block-local exclusive prefix
    if (t == 255) {
        g_bsum[blockIdx.x] = sm[255];
        __threadfence();
        atomicAdd(&g_tick, 1);
    }
    if (t == 0) {
        while (*(volatile int*)&g_tick < SBLK) { }
        __threadfence();
    }
    __syncthreads();
    // base = sum of bsum[0..blockIdx)
    int v2 = (t < blockIdx.x) ? g_bsum[t] : 0;   // blockIdx < SBLK <= 256
    sm[t] = v2;
    __syncthreads();
    for (int o = 128; o > 0; o >>= 1) {
        if (t < o) sm[t] += sm[t + o];
        __syncthreads();
    }
    int base = sm[0];
    if (n < NN) {
        int off = local + base;
        g_off[n]  = off;
        g_cur[n]  = off;
        g_invd[n] = 1.0f / (float)max(d, 1);
        if (n == NN - 1) g_off[NN] = off + d;
    }
}

// -------- compute d, pack [far|idx|j], scatter into CSR buckets ------------
__global__ void k_scatter(const int* __restrict__ ei, const float* __restrict__ pos) {
    int e = blockIdx.x * blockDim.x + threadIdx.x;      // NE threads exactly
    int i = ei[e];
    int j = ei[NE + e];
    float dx = pos[3 * i + 0] - pos[3 * j + 0];
    float dy = pos[3 * i + 1] - pos[3 * j + 1];
    float dz = pos[3 * i + 2] - pos[3 * j + 2];
    float d  = sqrtf(dx * dx + dy * dy + dz * dz);
    const float inv_step = (float)(TBL - 1) / DMAX;
    float tt = fminf(d * inv_step, (float)(TBL - 1));
    int pk;
    if (tt >= (float)(TBL - 1)) {
        pk = (int)(0x80000000u) | j;                    // far: bit31 set, idx=0
    } else {
        int idx = min((int)(tt + 0.5f), TBL - 1);       // nearest table row
        pk = (idx << 16) | j;
    }
    int p = atomicAdd(&g_cur[i], 1);
    g_pk[p] = pk;
}

// --- deterministic order: warp-per-node odd-even sort by packed word -------
// equal keys => identical payloads (same far/idx/j) => order irrelevant
__global__ void k_sort() {
    __shared__ int pk[8][SCAP];
    int tid  = threadIdx.x;
    int wid  = tid >> 5;
    int lane = tid & 31;
    int n    = (blockIdx.x * blockDim.x + tid) >> 5;    // 6250*8 = 50000 exact
    int lo = g_off[n], hi = g_off[n + 1];
    int d  = hi - lo;
    if (d <= 1) return;
    if (d > SCAP) {                                     // fallback (never hit @Poisson16)
        if (lane == 0) {
            for (int a = lo + 1; a < hi; a++) {
                int k = g_pk[a];
                int b = a - 1;
                while (b >= lo && g_pk[b] > k) {
                    g_pk[b + 1] = g_pk[b];
                    b--;
                }
                g_pk[b + 1] = k;
            }
        }
        return;
    }
    for (int u = lane; u < d; u += 32)
        pk[wid][u] = g_pk[lo + u];
    __syncwarp();
    for (int p = 0; p < d; p++) {
        int st = p & 1;
        for (int k2 = lane; 2 * k2 + 1 + st < d; k2 += 32) {
            int a = st + 2 * k2;
            int ka = pk[wid][a], kb = pk[wid][a + 1];
            if (ka > kb) {
                pk[wid][a] = kb;
                pk[wid][a + 1] = ka;
            }
        }
        __syncwarp();
    }
    for (int u = lane; u < d; u += 32)
        g_pk[lo + u] = pk[wid][u];
}

// -------- fused: build W_l(d) table + weight fragment images ---------------
// blocks [0, TABBLKS): table, 8 grid points per block, 128 threads.
// blocks [TABBLKS, TABBLKS+PWBLKS): prepw, 128 threads each.
__global__ void k_tabw(const float* __restrict__ fw1, const float* __restrict__ fb1,
                       const float* __restrict__ fw2, const float* __restrict__ fb2,
                       const float* __restrict__ uw1, const float* __restrict__ uw2,
                       const float* __restrict__ ow1, const float* __restrict__ ow2) {
    if (blockIdx.x >= TABBLKS) {
        // ---- prepw: mma B-fragment fp16 weight images ----
        // matrix m: m=2l -> uw1[l], m=2l+1 -> uw2[l] (l<6); 12 -> ow1; 13 -> ow2
        int idx  = (blockIdx.x - TABBLKS) * 128 + threadIdx.x;
        int lane = idx & 31;
        int t    = (idx >> 5) & 15;
        int s    = (idx >> 9) & 7;
        int m    = idx >> 12;
        const float* W;
        if (m < 12)       W = (m & 1) ? (uw2 + (size_t)(m >> 1) * 16384)
                                      : (uw1 + (size_t)(m >> 1) * 16384);
        else if (m == 12) W = ow1;
        else              W = ow2;
        int g    = lane >> 2;
        int tid2 = (lane & 3) * 2;
        int n    = t * 8 + g;
        int k0   = s * 16 + tid2;
        float v00 = W[(size_t)k0 * HID + n];
        float v01 = W[(size_t)(k0 + 1) * HID + n];
        float v10 = W[(size_t)(k0 + 8) * HID + n];
        float v11 = W[(size_t)(k0 + 9) * HID + n];
        uint2 o;
        o.x = packh2(v00, v01);
        o.y = packh2(v10, v11);
        *(uint2*)(g_wfrag + (size_t)idx * 2) = o;
        return;
    }
    // ---- table part ----
    const int PG = 8;
    int gid = blockIdx.x * PG;          // over NL*TBL
    int l   = gid / TBL;
    int g0  = gid - l * TBL;
    int c   = threadIdx.x;              // 128 threads
    __shared__ float rbf [PG][RBF];
    __shared__ float sspt[PG][HID];
    const float step   = DMAX / (float)(TBL - 1);
    const float cspace = 4.0f / 31.0f;

    for (int u = c; u < PG * RBF; u += HID) {
        int p = u >> 5, k = u & 31;
        float d = (float)(g0 + p) * step;
        float x = d - (float)k * cspace;
        rbf[p][k] = expf(-32.0f * x * x);
    }
    __syncthreads();

    float acc[PG];
    float b1 = fb1[l * HID + c];
    #pragma unroll
    for (int p = 0; p < PG; p++) acc[p] = b1;
    for (int k = 0; k < RBF; k++) {
        float f = fw1[(size_t)(l * RBF + k) * HID + c];
        #pragma unroll
        for (int p = 0; p < PG; p++) acc[p] = fmaf(rbf[p][k], f, acc[p]);
    }
    #pragma unroll
    for (int p = 0; p < PG; p++) sspt[p][c] = sspf(acc[p]);
    __syncthreads();

    float b2 = fb2[l * HID + c];
    #pragma unroll
    for (int p = 0; p < PG; p++) acc[p] = b2;
    for (int m = 0; m < HID; m++) {
        float f = fw2[(size_t)(l * HID + m) * HID + c];
        #pragma unroll
        for (int p = 0; p < PG; p++) acc[p] = fmaf(sspt[p][m], f, acc[p]);
    }
    #pragma unroll
    for (int p = 0; p < PG; p++)
        g_table[((size_t)l * TBL + g0 + p) * HID + c] = acc[p];
}

// --------- per-layer edge aggregation: one warp per node --------------------
// packed edge word: bit31=far, bits[16:28)=nearest table row, bits[0:16)=j.
// (R12/R14 body: per-edge uniform __ldg, fp32 gathers — fastest measured.)
__global__ void k_edge(int l) {
    int w    = (blockIdx.x * blockDim.x + threadIdx.x) >> 5;  // == node, exact
    int lane = threadIdx.x & 31;
    int lo = g_off[w], hi = g_off[w + 1];
    const float* tab = g_table + (size_t)l * TBL * HID;
    const float4 wlast = *(const float4*)(tab + (size_t)(TBL - 1) * HID + lane * 4);
    float nx = 0.f, ny = 0.f, nz = 0.f, nw = 0.f;   // near accum
    float fx = 0.f, fy = 0.f, fz = 0.f, fw = 0.f;   // far accum (h sum)
    for (int e = lo; e < hi; e++) {
        int p = __ldg(&g_pk[e]);
        int j = p & 0xFFFF;
        float4 hj = *(const float4*)(g_h + (size_t)j * HID + lane * 4);
        if (p < 0) {                                 // far (lane-uniform)
            fx += hj.x; fy += hj.y; fz += hj.z; fw += hj.w;
        } else {
            int idx = (p >> 16) & 0xFFF;
            float4 wl = *(const float4*)(tab + (size_t)idx * HID + lane * 4);
            nx = fmaf(hj.x, wl.x, nx);
            ny = fmaf(hj.y, wl.y, ny);
            nz = fmaf(hj.z, wl.z, nz);
            nw = fmaf(hj.w, wl.w, nw);
        }
    }
    float s = g_invd[w];
    float4 o;
    o.x = fmaf(fx, wlast.x, nx) * s;
    o.y = fmaf(fy, wlast.y, ny) * s;
    o.z = fmaf(fz, wlast.z, nz) * s;
    o.w = fmaf(fw, wlast.w, nw) * s;
    *(float4*)(g_aggr + (size_t)w * HID + lane * 4) = o;
}

// ---------- tensor-core fused 2-layer MLP (mma.sync fp16, 2-term split) ----
// Y = act2( ssp(X@W1+b1) @ W2 + b2 ). Each warp: 16 rows x 128 cols, K=128.
// ACT2=0: linear out to Y. ACT2=2: output block — ssp, dot(ow3), 4-lane
// reduce, atomicAdd into out[batch] (fused energy; no Y store).
template <int ACT2>
__global__ void __launch_bounds__(256, 1)
k_mlp_mma(const float* __restrict__ X,
          const u32* __restrict__ WF1, const float* __restrict__ B1,
          const u32* __restrict__ WF2, const float* __restrict__ B2,
          float* __restrict__ Y,
          const int* __restrict__ batch, const float* __restrict__ ow3,
          const float* __restrict__ ob3, float* __restrict__ out) {
    const int lane  = threadIdx.x & 31;
    const int warp  = (blockIdx.x * blockDim.x + threadIdx.x) >> 5;  // 0..3127
    const int rbase = warp * 16;                                     // < NNP
    const int g     = lane >> 2;
    const int tid2  = (lane & 3) * 2;
    const float* xr0 = X + (size_t)(rbase + g) * HID;
    const float* xr1 = X + (size_t)(rbase + g + 8) * HID;

    float acc[16][4];
    #pragma unroll
    for (int t = 0; t < 16; t++)
        #pragma unroll
        for (int q = 0; q < 4; q++) acc[t][q] = 0.f;

    // ---------------- stage 1 ----------------
    const uint2* wf1 = (const uint2*)WF1;
    #pragma unroll
    for (int s = 0; s < 8; s++) {
        int k0 = s * 16 + tid2;
        float2 x00 = *(const float2*)(xr0 + k0);
        float2 x10 = *(const float2*)(xr1 + k0);
        float2 x01 = *(const float2*)(xr0 + k0 + 8);
        float2 x11 = *(const float2*)(xr1 + k0 + 8);
        u32 ah[4], al[4];
        splith2(x00.x, x00.y, ah[0], al[0]);
        splith2(x10.x, x10.y, ah[1], al[1]);
        splith2(x01.x, x01.y, ah[2], al[2]);
        splith2(x11.x, x11.y, ah[3], al[3]);
        const uint2* bp = wf1 + (size_t)s * 512 + lane;
        #pragma unroll
        for (int t = 0; t < 16; t++) {
            uint2 b = __ldg(bp + t * 32);           // bh0,bh1
            mma_h(acc[t], ah, b.x, b.y);
            mma_h(acc[t], al, b.x, b.y);
        }
    }

    // ---- epilogue 1: bias + ssp, D frags -> stage-2 A frags (in register) --
    u32 a2h[8][4], a2l[8][4];
    #pragma unroll
    for (int s = 0; s < 8; s++) {
        #pragma unroll
        for (int hf = 0; hf < 2; hf++) {
            int t = 2 * s + hf;
            float2 bias = *(const float2*)(B1 + t * 8 + tid2);
            float d0 = sspf(acc[t][0] + bias.x);
            float d1 = sspf(acc[t][1] + bias.y);
            float d2 = sspf(acc[t][2] + bias.x);
            float d3 = sspf(acc[t][3] + bias.y);
            splith2(d0, d1, a2h[s][2 * hf + 0], a2l[s][2 * hf + 0]);
            splith2(d2, d3, a2h[s][2 * hf + 1], a2l[s][2 * hf + 1]);
        }
    }

    #pragma unroll
    for (int t = 0; t < 16; t++)
        #pragma unroll
        for (int q = 0; q < 4; q++) acc[t][q] = 0.f;

    // ---------------- stage 2 ----------------
    const uint2* wf2 = (const uint2*)WF2;
    #pragma unroll
    for (int s = 0; s < 8; s++) {
        const uint2* bp = wf2 + (size_t)s * 512 + lane;
        #pragma unroll
        for (int t = 0; t < 16; t++) {
            uint2 b = __ldg(bp + t * 32);
            mma_h(acc[t], a2h[s], b.x, b.y);
            mma_h(acc[t], a2l[s], b.x, b.y);
        }
    }

    // ---- epilogue 2 ----
    if (ACT2 == 2) {
        // output block: ssp, dot with ow3, reduce 4 lanes per row, atomic add
        float p0 = 0.f, p1 = 0.f;
        #pragma unroll
        for (int t = 0; t < 16; t++) {
            int c0 = t * 8 + tid2;
            float2 bias = *(const float2*)(B2 + c0);
            float2 w3   = make_float2(__ldg(&ow3[c0]), __ldg(&ow3[c0 + 1]));
            float o0 = sspf(acc[t][0] + bias.x);
            float o1 = sspf(acc[t][1] + bias.y);
            float o2 = sspf(acc[t][2] + bias.x);
            float o3 = sspf(acc[t][3] + bias.y);
            p0 = fmaf(o0, w3.x, fmaf(o1, w3.y, p0));
            p1 = fmaf(o2, w3.x, fmaf(o3, w3.y, p1));
        }
        p0 += __shfl_xor_sync(0xffffffffu, p0, 1);
        p0 += __shfl_xor_sync(0xffffffffu, p0, 2);
        p1 += __shfl_xor_sync(0xffffffffu, p1, 1);
        p1 += __shfl_xor_sync(0xffffffffu, p1, 2);
        if ((lane & 3) == 0) {
            float b3 = __ldg(&ob3[0]);
            int r0 = rbase + g;
            int r1 = rbase + g + 8;
            if (r0 < NN) atomicAdd(&out[__ldg(&batch[r0])], p0 + b3);
            if (r1 < NN) atomicAdd(&out[__ldg(&batch[r1])], p1 + b3);
        }
    } else {
        float* yr0 = Y + (size_t)(rbase + g) * HID;
        float* yr1 = Y + (size_t)(rbase + g + 8) * HID;
        #pragma unroll
        for (int t = 0; t < 16; t++) {
            float2 bias = *(const float2*)(B2 + t * 8 + tid2);
            float o0 = acc[t][0] + bias.x;
            float o1 = acc[t][1] + bias.y;
            float o2 = acc[t][2] + bias.x;
            float o3 = acc[t][3] + bias.y;
            *(float2*)(yr0 + t * 8 + tid2) = make_float2(o0, o1);
            *(float2*)(yr1 + t * 8 + tid2) = make_float2(o2, o3);
        }
    }
}

// ---------------- launch ----------------
extern "C" void kernel_launch(void* const* d_in, const int* in_sizes, int n_in,
                              void* d_out, int out_size) {
    const int*   z     = (const int*)  d_in[0];
    const float* pos   = (const float*)d_in[1];
    const int*   ei    = (const int*)  d_in[2];
    const int*   batch = (const int*)  d_in[3];
    const float* embed = (const float*)d_in[4];
    const float* fw1   = (const float*)d_in[5];
    const float* fb1   = (const float*)d_in[6];
    const float* fw2   = (const float*)d_in[7];
    const float* fb2   = (const float*)d_in[8];
    const float* uw1   = (const float*)d_in[9];
    const float* ub1   = (const float*)d_in[10];
    const float* uw2   = (const float*)d_in[11];
    const float* ub2   = (const float*)d_in[12];
    const float* ow1   = (const float*)d_in[13];
    const float* ob1   = (const float*)d_in[14];
    const float* ow2   = (const float*)d_in[15];
    const float* ob2   = (const float*)d_in[16];
    const float* ow3   = (const float*)d_in[17];
    const float* ob3   = (const float*)d_in[18];
    float* out = (float*)d_out;

    float *p_h = nullptr, *p_aggr = nullptr;
    u32*   p_wf = nullptr;
    cudaGetSymbolAddress((void**)&p_h,    g_h);
    cudaGetSymbolAddress((void**)&p_aggr, g_aggr);
    cudaGetSymbolAddress((void**)&p_wf,   g_wfrag);

    // preprocessing (once per launch, amortized over 6 layers)
    k_init   <<<(NNP * 32) / 256, 256>>>(z, embed, out);
    k_deg    <<<NE / 256, 256>>>(ei);
    k_scanf  <<<SBLK, 256>>>();
    k_scatter<<<NE / 256, 256>>>(ei, pos);
    k_sort   <<<(NN * 32) / 256, 256>>>();
    k_tabw   <<<TABBLKS + PWBLKS, 128>>>(fw1, fb1, fw2, fb2, uw1, uw2, ow1, ow2);

    const int mma_blocks  = NNP / 128;            // 391 blocks x 8 warps x 16 rows
    const int warp_blocks = (NN * 32) / 256;

    for (int l = 0; l < NL; l++) {
        k_edge<<<warp_blocks, 256>>>(l);
        k_mlp_mma<0><<<mma_blocks, 256>>>(
            p_aggr,
            p_wf + (size_t)(2 * l)     * 8192, ub1 + (size_t)l * HID,
            p_wf + (size_t)(2 * l + 1) * 8192, ub2 + (size_t)l * HID,
            p_h, nullptr, nullptr, nullptr, nullptr);
    }
    // output block fused with energy reduction
    k_mlp_mma<2><<<mma_blocks, 256>>>(
        p_h,
        p_wf + (size_t)12 * 8192, ob1,
        p_wf + (size_t)13 * 8192, ob2,
        nullptr, batch, ow3, ob3, out);
}

// round 17
// speedup vs baseline: 1.0859x; 1.0291x over previous
#include <cuda_runtime.h>
#include <cuda_fp16.h>
#include <math.h>

#define NN    50000      // nodes
#define NNP   50048      // padded to 16*8*391
#define NE    800000     // edges
#define NG    512        // graphs
#define HID   128
#define RBF   32
#define NL    6
#define TBL   320        // LUT grid points per layer (160KB/layer: L1-resident)
#define DMAX  5.0f       // beyond this, rbf == 0 to fp32 precision
#define SBLK  196        // scan blocks (196*256 >= NN)
#define SCAP  128        // per-warp smem sort capacity
#define INITBLKS ((NNP * 32) / 256)         // 6256 init blocks
#define DEGBLKS  (NE / 256)                 // 3125 deg blocks
#define TABBLKS ((NL * TBL) / 8)            // 240 table blocks
#define PWBLKS  ((14 * 8 * 16 * 32) / 128)  // 448 prepw blocks (128 thr)

typedef unsigned long long u64;
typedef unsigned int u32;

// ---------------- device scratch (static allocations only) ----------------
__device__ float g_h    [NNP * HID];       // node features (padded, tail zero)
__device__ float g_aggr [NNP * HID];       // aggregated messages
__device__ float g_table[NL * TBL * HID];  // W_l(d) lookup table
__device__ int   g_deg  [NN];              // zero at entry (self-cleaned by scanf)
__device__ float g_invd [NN];
__device__ int   g_off  [NN + 1];
__device__ int   g_cur  [NN];
__device__ int   g_bsum [SBLK];            // scan partials
__device__ int   g_tick;                   // scan grid-barrier ticket
__device__ int   g_pk   [NE];              // packed edge: [far(1)|idx(12)|j(16)]
// mma-fragment-layout fp16 weight images (hi only):
// [m:14][s:8][t:16][lane:32][2 x u32: bh0,bh1]
__device__ u32   g_wfrag[14 * 8 * 16 * 32 * 2];

__device__ __forceinline__ float sspf(float x) {
    return fmaxf(x, 0.0f) + log1pf(expf(-fabsf(x))) - 0.5f;
}

// pack two floats as f16x2
__device__ __forceinline__ u32 packh2(float x, float y) {
    __half2 h = __floats2half2_rn(x, y);
    return *reinterpret_cast<u32*>(&h);
}
// fp16 hi/lo split of a float2 into packed f16x2 pair
__device__ __forceinline__ void splith2(float x, float y, u32& hi, u32& lo) {
    __half hx = __float2half_rn(x);
    __half hy = __float2half_rn(y);
    float rx = x - __half2float(hx);
    float ry = y - __half2float(hy);
    __half2 hh = __halves2half2(hx, hy);
    hi = *reinterpret_cast<u32*>(&hh);
    lo = packh2(rx, ry);
}

__device__ __forceinline__ void mma_h(float c[4], const u32 a[4], u32 b0, u32 b1) {
    asm volatile(
        "mma.sync.aligned.m16n8k16.row.col.f32.f16.f16.f32 "
        "{%0,%1,%2,%3}, {%4,%5,%6,%7}, {%8,%9}, {%0,%1,%2,%3};"
        : "+f"(c[0]), "+f"(c[1]), "+f"(c[2]), "+f"(c[3])
        : "r"(a[0]), "r"(a[1]), "r"(a[2]), "r"(a[3]), "r"(b0), "r"(b1));
}

// --- fused init + degree count (block-range split) -------------------------
// init part: h = embed[z], zero tick/tails/energy out. g_deg is NOT zeroed
// here — it is zero at entry (static zero-init on first run; self-cleaned by
// k_scanf on every run), so the deg part can atomically count concurrently.
__global__ void k_initdeg(const int* __restrict__ z, const float* __restrict__ embed,
                          const int* __restrict__ ei, float* __restrict__ out) {
    if (blockIdx.x >= INITBLKS) {
        int e = (blockIdx.x - INITBLKS) * 256 + threadIdx.x;  // NE exactly
        atomicAdd(&g_deg[ei[e]], 1);
        return;
    }
    int tid  = blockIdx.x * blockDim.x + threadIdx.x;   // NNP*32 threads exactly
    if (tid < NG) out[tid] = 0.0f;                      // energy accumulator
    if (tid == 0) g_tick = 0;                           // scan barrier reset
    int n    = tid >> 5;
    int lane = tid & 31;
    if (n >= NN) {                                      // padded tail: keep zero
        float4 zf = make_float4(0.f, 0.f, 0.f, 0.f);
        *(float4*)(g_h    + (size_t)n * HID + lane * 4) = zf;
        *(float4*)(g_aggr + (size_t)n * HID + lane * 4) = zf;
        return;
    }
    int zz = z[n];
    float4 v = *(const float4*)(embed + (size_t)zz * HID + lane * 4);
    *(float4*)(g_h + (size_t)n * HID + lane * 4) = v;
}

// ------ single-kernel scan: 196 co-resident blocks + ticket grid barrier ---
// Also self-cleans g_deg to zero for the next graph replay.
__global__ void k_scanf() {
    __shared__ int sm[256];
    int t = threadIdx.x;
    int n = blockIdx.x * 256 + t;
    int d = (n < NN) ? g_deg[n] : 0;
    if (n < NN) g_deg[n] = 0;               // self-clean for next replay
    sm[t] = d;
    __syncthreads();
    for (int o = 1; o < 256; o <<= 1) {
        int v = (t >= o) ? sm[t - o] : 0;
        __syncthreads();
        sm[t] += v;
        __syncthreads();
    }
    int local = sm[t] - d;                  // block-local exclusive prefix
    if (t == 255) {
        g_bsum[blockIdx.x] = sm[255];
        __threadfence();
        atomicAdd(&g_tick, 1);
    }
    if (t == 0) {
        while (*(volatile int*)&g_tick < SBLK) { }
        __threadfence();
    }
    __syncthreads();
    // base = sum of bsum[0..blockIdx)
    int v2 = (t < blockIdx.x) ? g_bsum[t] : 0;   // blockIdx < SBLK <= 256
    sm[t] = v2;
    __syncthreads();
    for (int o = 128; o > 0; o >>= 1) {
        if (t < o) sm[t] += sm[t + o];
        __syncthreads();
    }
    int base = sm[0];
    if (n < NN) {
        int off = local + base;
        g_off[n]  = off;
        g_cur[n]  = off;
        g_invd[n] = 1.0f / (float)max(d, 1);
        if (n == NN - 1) g_off[NN] = off + d;
    }
}

// -------- compute d, pack [far|idx|j], scatter into CSR buckets ------------
__global__ void k_scatter(const int* __restrict__ ei, const float* __restrict__ pos) {
    int e = blockIdx.x * blockDim.x + threadIdx.x;      // NE threads exactly
    int i = ei[e];
    int j = ei[NE + e];
    float dx = pos[3 * i + 0] - pos[3 * j + 0];
    float dy = pos[3 * i + 1] - pos[3 * j + 1];
    float dz = pos[3 * i + 2] - pos[3 * j + 2];
    float d  = sqrtf(dx * dx + dy * dy + dz * dz);
    const float inv_step = (float)(TBL - 1) / DMAX;
    float tt = fminf(d * inv_step, (float)(TBL - 1));
    int pk;
    if (tt >= (float)(TBL - 1)) {
        pk = (int)(0x80000000u) | j;                    // far: bit31 set, idx=0
    } else {
        int idx = min((int)(tt + 0.5f), TBL - 1);       // nearest table row
        pk = (idx << 16) | j;
    }
    int p = atomicAdd(&g_cur[i], 1);
    g_pk[p] = pk;
}

// --- deterministic order: warp-per-node odd-even sort by packed word -------
// equal keys => identical payloads (same far/idx/j) => order irrelevant
__global__ void k_sort() {
    __shared__ int pk[8][SCAP];
    int tid  = threadIdx.x;
    int wid  = tid >> 5;
    int lane = tid & 31;
    int n    = (blockIdx.x * blockDim.x + tid) >> 5;    // 6250*8 = 50000 exact
    int lo = g_off[n], hi = g_off[n + 1];
    int d  = hi - lo;
    if (d <= 1) return;
    if (d > SCAP) {                                     // fallback (never hit @Poisson16)
        if (lane == 0) {
            for (int a = lo + 1; a < hi; a++) {
                int k = g_pk[a];
                int b = a - 1;
                while (b >= lo && g_pk[b] > k) {
                    g_pk[b + 1] = g_pk[b];
                    b--;
                }
                g_pk[b + 1] = k;
            }
        }
        return;
    }
    for (int u = lane; u < d; u += 32)
        pk[wid][u] = g_pk[lo + u];
    __syncwarp();
    for (int p = 0; p < d; p++) {
        int st = p & 1;
        for (int k2 = lane; 2 * k2 + 1 + st < d; k2 += 32) {
            int a = st + 2 * k2;
            int ka = pk[wid][a], kb = pk[wid][a + 1];
            if (ka > kb) {
                pk[wid][a] = kb;
                pk[wid][a + 1] = ka;
            }
        }
        __syncwarp();
    }
    for (int u = lane; u < d; u += 32)
        g_pk[lo + u] = pk[wid][u];
}

// -------- fused: build W_l(d) table + weight fragment images ---------------
// blocks [0, TABBLKS): table, 8 grid points per block, 128 threads.
// blocks [TABBLKS, TABBLKS+PWBLKS): prepw, 128 threads each.
__global__ void k_tabw(const float* __restrict__ fw1, const float* __restrict__ fb1,
                       const float* __restrict__ fw2, const float* __restrict__ fb2,
                       const float* __restrict__ uw1, const float* __restrict__ uw2,
                       const float* __restrict__ ow1, const float* __restrict__ ow2) {
    if (blockIdx.x >= TABBLKS) {
        // ---- prepw: mma B-fragment fp16 weight images ----
        // matrix m: m=2l -> uw1[l], m=2l+1 -> uw2[l] (l<6); 12 -> ow1; 13 -> ow2
        int idx  = (blockIdx.x - TABBLKS) * 128 + threadIdx.x;
        int lane = idx & 31;
        int t    = (idx >> 5) & 15;
        int s    = (idx >> 9) & 7;
        int m    = idx >> 12;
        const float* W;
        if (m < 12)       W = (m & 1) ? (uw2 + (size_t)(m >> 1) * 16384)
                                      : (uw1 + (size_t)(m >> 1) * 16384);
        else if (m == 12) W = ow1;
        else              W = ow2;
        int g    = lane >> 2;
        int tid2 = (lane & 3) * 2;
        int n    = t * 8 + g;
        int k0   = s * 16 + tid2;
        float v00 = W[(size_t)k0 * HID + n];
        float v01 = W[(size_t)(k0 + 1) * HID + n];
        float v10 = W[(size_t)(k0 + 8) * HID + n];
        float v11 = W[(size_t)(k0 + 9) * HID + n];
        uint2 o;
        o.x = packh2(v00, v01);
        o.y = packh2(v10, v11);
        *(uint2*)(g_wfrag + (size_t)idx * 2) = o;
        return;
    }
    // ---- table part ----
    const int PG = 8;
    int gid = blockIdx.x * PG;          // over NL*TBL
    int l   = gid / TBL;
    int g0  = gid - l * TBL;
    int c   = threadIdx.x;              // 128 threads
    __shared__ float rbf [PG][RBF];
    __shared__ float sspt[PG][HID];
    const float step   = DMAX / (float)(TBL - 1);
    const float cspace = 4.0f / 31.0f;

    for (int u = c; u < PG * RBF; u += HID) {
        int p = u >> 5, k = u & 31;
        float d = (float)(g0 + p) * step;
        float x = d - (float)k * cspace;
        rbf[p][k] = expf(-32.0f * x * x);
    }
    __syncthreads();

    float acc[PG];
    float b1 = fb1[l * HID + c];
    #pragma unroll
    for (int p = 0; p < PG; p++) acc[p] = b1;
    for (int k = 0; k < RBF; k++) {
        float f = fw1[(size_t)(l * RBF + k) * HID + c];
        #pragma unroll
        for (int p = 0; p < PG; p++) acc[p] = fmaf(rbf[p][k], f, acc[p]);
    }
    #pragma unroll
    for (int p = 0; p < PG; p++) sspt[p][c] = sspf(acc[p]);
    __syncthreads();

    float b2 = fb2[l * HID + c];
    #pragma unroll
    for (int p = 0; p < PG; p++) acc[p] = b2;
    for (int m = 0; m < HID; m++) {
        float f = fw2[(size_t)(l * HID + m) * HID + c];
        #pragma unroll
        for (int p = 0; p < PG; p++) acc[p] = fmaf(sspt[p][m], f, acc[p]);
    }
    #pragma unroll
    for (int p = 0; p < PG; p++)
        g_table[((size_t)l * TBL + g0 + p) * HID + c] = acc[p];
}

// --------- per-layer edge aggregation: one warp per node --------------------
// packed edge word: bit31=far, bits[16:28)=nearest table row, bits[0:16)=j.
// table is 160KB/layer -> L1-resident after warmup; near-path wl loads become
// L1 hits instead of ~250cyc L2 round trips.
__global__ void k_edge(int l) {
    int w    = (blockIdx.x * blockDim.x + threadIdx.x) >> 5;  // == node, exact
    int lane = threadIdx.x & 31;
    int lo = g_off[w], hi = g_off[w + 1];
    const float* tab = g_table + (size_t)l * TBL * HID;
    const float4 wlast = *(const float4*)(tab + (size_t)(TBL - 1) * HID + lane * 4);
    float nx = 0.f, ny = 0.f, nz = 0.f, nw = 0.f;   // near accum
    float fx = 0.f, fy = 0.f, fz = 0.f, fw = 0.f;   // far accum (h sum)
    for (int e = lo; e < hi; e++) {
        int p = __ldg(&g_pk[e]);
        int j = p & 0xFFFF;
        float4 hj = *(const float4*)(g_h + (size_t)j * HID + lane * 4);
        if (p < 0) {                                 // far (lane-uniform)
            fx += hj.x; fy += hj.y; fz += hj.z; fw += hj.w;
        } else {
            int idx = (p >> 16) & 0xFFF;
            float4 wl = *(const float4*)(tab + (size_t)idx * HID + lane * 4);
            nx = fmaf(hj.x, wl.x, nx);
            ny = fmaf(hj.y, wl.y, ny);
            nz = fmaf(hj.z, wl.z, nz);
            nw = fmaf(hj.w, wl.w, nw);
        }
    }
    float s = g_invd[w];
    float4 o;
    o.x = fmaf(fx, wlast.x, nx) * s;
    o.y = fmaf(fy, wlast.y, ny) * s;
    o.z = fmaf(fz, wlast.z, nz) * s;
    o.w = fmaf(fw, wlast.w, nw) * s;
    *(float4*)(g_aggr + (size_t)w * HID + lane * 4) = o;
}

// ---------- tensor-core fused 2-layer MLP (mma.sync fp16, 2-term split) ----
// Y = act2( ssp(X@W1+b1) @ W2 + b2 ). Each warp: 16 rows x 128 cols, K=128.
// ACT2=0: linear out to Y. ACT2=2: output block — ssp, dot(ow3), 4-lane
// reduce, atomicAdd into out[batch] (fused energy; no Y store).
template <int ACT2>
__global__ void __launch_bounds__(256, 1)
k_mlp_mma(const float* __restrict__ X,
          const u32* __restrict__ WF1, const float* __restrict__ B1,
          const u32* __restrict__ WF2, const float* __restrict__ B2,
          float* __restrict__ Y,
          const int* __restrict__ batch, const float* __restrict__ ow3,
          const float* __restrict__ ob3, float* __restrict__ out) {
    const int lane  = threadIdx.x & 31;
    const int warp  = (blockIdx.x * blockDim.x + threadIdx.x) >> 5;  // 0..3127
    const int rbase = warp * 16;                                     // < NNP
    const int g     = lane >> 2;
    const int tid2  = (lane & 3) * 2;
    const float* xr0 = X + (size_t)(rbase + g) * HID;
    const float* xr1 = X + (size_t)(rbase + g + 8) * HID;

    float acc[16][4];
    #pragma unroll
    for (int t = 0; t < 16; t++)
        #pragma unroll
        for (int q = 0; q < 4; q++) acc[t][q] = 0.f;

    // ---------------- stage 1 ----------------
    const uint2* wf1 = (const uint2*)WF1;
    #pragma unroll
    for (int s = 0; s < 8; s++) {
        int k0 = s * 16 + tid2;
        float2 x00 = *(const float2*)(xr0 + k0);
        float2 x10 = *(const float2*)(xr1 + k0);
        float2 x01 = *(const float2*)(xr0 + k0 + 8);
        float2 x11 = *(const float2*)(xr1 + k0 + 8);
        u32 ah[4], al[4];
        splith2(x00.x, x00.y, ah[0], al[0]);
        splith2(x10.x, x10.y, ah[1], al[1]);
        splith2(x01.x, x01.y, ah[2], al[2]);
        splith2(x11.x, x11.y, ah[3], al[3]);
        const uint2* bp = wf1 + (size_t)s * 512 + lane;
        #pragma unroll
        for (int t = 0; t < 16; t++) {
            uint2 b = __ldg(bp + t * 32);           // bh0,bh1
            mma_h(acc[t], ah, b.x, b.y);
            mma_h(acc[t], al, b.x, b.y);
        }
    }

    // ---- epilogue 1: bias + ssp, D frags -> stage-2 A frags (in register) --
    u32 a2h[8][4], a2l[8][4];
    #pragma unroll
    for (int s = 0; s < 8; s++) {
        #pragma unroll
        for (int hf = 0; hf < 2; hf++) {
            int t = 2 * s + hf;
            float2 bias = *(const float2*)(B1 + t * 8 + tid2);
            float d0 = sspf(acc[t][0] + bias.x);
            float d1 = sspf(acc[t][1] + bias.y);
            float d2 = sspf(acc[t][2] + bias.x);
            float d3 = sspf(acc[t][3] + bias.y);
            splith2(d0, d1, a2h[s][2 * hf + 0], a2l[s][2 * hf + 0]);
            splith2(d2, d3, a2h[s][2 * hf + 1], a2l[s][2 * hf + 1]);
        }
    }

    #pragma unroll
    for (int t = 0; t < 16; t++)
        #pragma unroll
        for (int q = 0; q < 4; q++) acc[t][q] = 0.f;

    // ---------------- stage 2 ----------------
    const uint2* wf2 = (const uint2*)WF2;
    #pragma unroll
    for (int s = 0; s < 8; s++) {
        const uint2* bp = wf2 + (size_t)s * 512 + lane;
        #pragma unroll
        for (int t = 0; t < 16; t++) {
            uint2 b = __ldg(bp + t * 32);
            mma_h(acc[t], a2h[s], b.x, b.y);
            mma_h(acc[t], a2l[s], b.x, b.y);
        }
    }

    // ---- epilogue 2 ----
    if (ACT2 == 2) {
        // output block: ssp, dot with ow3, reduce 4 lanes per row, atomic add
        float p0 = 0.f, p1 = 0.f;
        #pragma unroll
        for (int t = 0; t < 16; t++) {
            int c0 = t * 8 + tid2;
            float2 bias = *(const float2*)(B2 + c0);
            float2 w3   = make_float2(__ldg(&ow3[c0]), __ldg(&ow3[c0 + 1]));
            float o0 = sspf(acc[t][0] + bias.x);
            float o1 = sspf(acc[t][1] + bias.y);
            float o2 = sspf(acc[t][2] + bias.x);
            float o3 = sspf(acc[t][3] + bias.y);
            p0 = fmaf(o0, w3.x, fmaf(o1, w3.y, p0));
            p1 = fmaf(o2, w3.x, fmaf(o3, w3.y, p1));
        }
        p0 += __shfl_xor_sync(0xffffffffu, p0, 1);
        p0 += __shfl_xor_sync(0xffffffffu, p0, 2);
        p1 += __shfl_xor_sync(0xffffffffu, p1, 1);
        p1 += __shfl_xor_sync(0xffffffffu, p1, 2);
        if ((lane & 3) == 0) {
            float b3 = __ldg(&ob3[0]);
            int r0 = rbase + g;
            int r1 = rbase + g + 8;
            if (r0 < NN) atomicAdd(&out[__ldg(&batch[r0])], p0 + b3);
            if (r1 < NN) atomicAdd(&out[__ldg(&batch[r1])], p1 + b3);
        }
    } else {
        float* yr0 = Y + (size_t)(rbase + g) * HID;
        float* yr1 = Y + (size_t)(rbase + g + 8) * HID;
        #pragma unroll
        for (int t = 0; t < 16; t++) {
            float2 bias = *(const float2*)(B2 + t * 8 + tid2);
            float o0 = acc[t][0] + bias.x;
            float o1 = acc[t][1] + bias.y;
            float o2 = acc[t][2] + bias.x;
            float o3 = acc[t][3] + bias.y;
            *(float2*)(yr0 + t * 8 + tid2) = make_float2(o0, o1);
            *(float2*)(yr1 + t * 8 + tid2) = make_float2(o2, o3);
        }
    }
}

// ---------------- launch ----------------
extern "C" void kernel_launch(void* const* d_in, const int* in_sizes, int n_in,
                              void* d_out, int out_size) {
    const int*   z     = (const int*)  d_in[0];
    const float* pos   = (const float*)d_in[1];
    const int*   ei    = (const int*)  d_in[2];
    const int*   batch = (const int*)  d_in[3];
    const float* embed = (const float*)d_in[4];
    const float* fw1   = (const float*)d_in[5];
    const float* fb1   = (const float*)d_in[6];
    const float* fw2   = (const float*)d_in[7];
    const float* fb2   = (const float*)d_in[8];
    const float* uw1   = (const float*)d_in[9];
    const float* ub1   = (const float*)d_in[10];
    const float* uw2   = (const float*)d_in[11];
    const float* ub2   = (const float*)d_in[12];
    const float* ow1   = (const float*)d_in[13];
    const float* ob1   = (const float*)d_in[14];
    const float* ow2   = (const float*)d_in[15];
    const float* ob2   = (const float*)d_in[16];
    const float* ow3   = (const float*)d_in[17];
    const float* ob3   = (const float*)d_in[18];
    float* out = (float*)d_out;

    float *p_h = nullptr, *p_aggr = nullptr;
    u32*   p_wf = nullptr;
    cudaGetSymbolAddress((void**)&p_h,    g_h);
    cudaGetSymbolAddress((void**)&p_aggr, g_aggr);
    cudaGetSymbolAddress((void**)&p_wf,   g_wfrag);

    // preprocessing (once per launch, amortized over 6 layers)
    k_initdeg<<<INITBLKS + DEGBLKS, 256>>>(z, embed, ei, out);
    k_scanf  <<<SBLK, 256>>>();
    k_scatter<<<NE / 256, 256>>>(ei, pos);
    k_sort   <<<(NN * 32) / 256, 256>>>();
    k_tabw   <<<TABBLKS + PWBLKS, 128>>>(fw1, fb1, fw2, fb2, uw1, uw2, ow1, ow2);

    const int mma_blocks  = NNP / 128;            // 391 blocks x 8 warps x 16 rows
    const int warp_blocks = (NN * 32) / 256;

    for (int l = 0; l < NL; l++) {
        k_edge<<<warp_blocks, 256>>>(l);
        k_mlp_mma<0><<<mma_blocks, 256>>>(
            p_aggr,
            p_wf + (size_t)(2 * l)     * 8192, ub1 + (size_t)l * HID,
            p_wf + (size_t)(2 * l + 1) * 8192, ub2 + (size_t)l * HID,
            p_h, nullptr, nullptr, nullptr, nullptr);
    }
    // output block fused with energy reduction
    k_mlp_mma<2><<<mma_blocks, 256>>>(
        p_h,
        p_wf + (size_t)12 * 8192, ob1,
        p_wf + (size_t)13 * 8192, ob2,
        nullptr, batch, ow3, ob3, out);
}